// round 17
// baseline (speedup 1.0000x reference)
#include <cuda_runtime.h>
#include <cuda_bf16.h>
#include <cstdint>

constexpr int C_   = 192;
constexpr int H_   = 192;
constexpr int W_   = 192;
constexpr int SS_  = 4;
constexpr int NWIN = 8 * 24 * 24;   // 4608
constexpr int HW_  = H_ * W_;

// pre-split weights / activations: [row][24] uint4 (8 bf16 each)
__device__ uint4 g_wqh[576 * 24], g_wql[576 * 24];
__device__ uint4 g_wph[192 * 24], g_wpl[192 * 24];
__device__ uint4 g_xhi[(size_t)NWIN * 1536], g_xlo[(size_t)NWIN * 1536];
__device__ uint4 g_ahi[(size_t)NWIN * 1536], g_alo[(size_t)NWIN * 1536];
// qkv output: bf16 hi/lo planes [b_][s][h]: 64 rows x 32 d (uint32 = 2 bf16)
__device__ uint32_t g_sh32[(size_t)NWIN * 18 * 1024];
__device__ uint32_t g_sl32[(size_t)NWIN * 18 * 1024];

typedef unsigned long long ull;

__device__ __forceinline__ uint32_t smem_u32(const void* p) {
    uint32_t a;
    asm("{ .reg .u64 t; cvta.to.shared.u64 t, %1; cvt.u32.u64 %0, t; }"
        : "=r"(a) : "l"(p));
    return a;
}
__device__ __forceinline__ void ldsm4(uint32_t* r, uint32_t addr) {
    asm volatile("ldmatrix.sync.aligned.m8n8.x4.shared.b16 {%0,%1,%2,%3}, [%4];"
                 : "=r"(r[0]), "=r"(r[1]), "=r"(r[2]), "=r"(r[3]) : "r"(addr));
}
__device__ __forceinline__ void ldsm4t(uint32_t* r, uint32_t addr) {
    asm volatile("ldmatrix.sync.aligned.m8n8.x4.trans.shared.b16 {%0,%1,%2,%3}, [%4];"
                 : "=r"(r[0]), "=r"(r[1]), "=r"(r[2]), "=r"(r[3]) : "r"(addr));
}
__device__ __forceinline__ void mma16816(float* d, const uint32_t* a,
                                         uint32_t b0, uint32_t b1) {
    asm volatile(
        "mma.sync.aligned.m16n8k16.row.col.f32.bf16.bf16.f32 "
        "{%0,%1,%2,%3}, {%4,%5,%6,%7}, {%8,%9}, {%0,%1,%2,%3};"
        : "+f"(d[0]), "+f"(d[1]), "+f"(d[2]), "+f"(d[3])
        : "r"(a[0]), "r"(a[1]), "r"(a[2]), "r"(a[3]), "r"(b0), "r"(b1));
}
__device__ __forceinline__ void split2(float a, float b, uint32_t& hi, uint32_t& lo) {
    __nv_bfloat16 ah = __float2bfloat16(a);
    __nv_bfloat16 bh = __float2bfloat16(b);
    __nv_bfloat16 al = __float2bfloat16(a - __bfloat162float(ah));
    __nv_bfloat16 bl = __float2bfloat16(b - __bfloat162float(bh));
    hi = (uint32_t)__bfloat16_as_ushort(ah) | ((uint32_t)__bfloat16_as_ushort(bh) << 16);
    lo = (uint32_t)__bfloat16_as_ushort(al) | ((uint32_t)__bfloat16_as_ushort(bl) << 16);
}

#define CP_ASYNC16(dst, src) \
    asm volatile("cp.async.cg.shared.global [%0], [%1], 16;" :: "r"(dst), "l"(src))
#define CP_COMMIT() asm volatile("cp.async.commit_group;" ::: "memory")
#define CP_WAIT0()  asm volatile("cp.async.wait_group 0;"  ::: "memory")

// =====================================================================
// Setup A: split weights into bf16 hi/lo
// =====================================================================
__global__ void k_split_w(const float* __restrict__ qw, const float* __restrict__ pw) {
    int i = blockIdx.x * 256 + threadIdx.x;      // 0 .. 18431
    const float* src;
    uint4 *dh, *dl;
    int base;
    if (i < 13824) { src = qw; dh = g_wqh; dl = g_wql; base = i; }
    else           { src = pw; dh = g_wph; dl = g_wpl; base = i - 13824; }
    int row = base / 24, c = base % 24;
    const float* p = src + row * 192 + c * 8;
    float4 v0 = *(const float4*)p;
    float4 v1 = *(const float4*)(p + 4);
    uint32_t hi[4], lo[4];
    split2(v0.x, v0.y, hi[0], lo[0]);
    split2(v0.z, v0.w, hi[1], lo[1]);
    split2(v1.x, v1.y, hi[2], lo[2]);
    split2(v1.z, v1.w, hi[3], lo[3]);
    dh[base] = make_uint4(hi[0], hi[1], hi[2], hi[3]);
    dl[base] = make_uint4(lo[0], lo[1], lo[2], lo[3]);
}

// =====================================================================
// Setup B: gather rolled windows + split x into bf16 hi/lo panels
// =====================================================================
__global__ __launch_bounds__(256)
void k_split_x(const float* __restrict__ x) {
    __shared__ int soff[64];
    const int b_  = blockIdx.x;
    const int b   = b_ / 576;
    const int tid = threadIdx.x;
    if (tid < 64) {
        int wh = (b_ % 576) / 24, ww = b_ % 24;
        int sh = wh * 8 + (tid >> 3) + SS_; if (sh >= H_) sh -= H_;
        int sw = ww * 8 + (tid & 7)  + SS_; if (sw >= W_) sw -= W_;
        soff[tid] = sh * W_ + sw;
    }
    __syncthreads();
    const float* xb = x + (size_t)b * C_ * HW_;
    uint4* dh = g_xhi + (size_t)b_ * 1536;
    uint4* dl = g_xlo + (size_t)b_ * 1536;
    #pragma unroll
    for (int u = 0; u < 6; u++) {
        int i = tid + u * 256;
        int t = i / 24, c = i - t * 24;
        float v[8];
        #pragma unroll
        for (int j = 0; j < 8; j++) v[j] = xb[(c * 8 + j) * HW_ + soff[t]];
        uint32_t hi[4], lo[4];
        #pragma unroll
        for (int p = 0; p < 4; p++) split2(v[2 * p], v[2 * p + 1], hi[p], lo[p]);
        dh[i] = make_uint4(hi[0], hi[1], hi[2], hi[3]);
        dl[i] = make_uint4(lo[0], lo[1], lo[2], lo[3]);
    }
}

// =====================================================================
// Kernel 1: chunk-persistent QKV GEMM; epilogue emits bf16 hi/lo planes
// =====================================================================
constexpr int QP_W  = 144;
constexpr int QP_NG = 32;

__global__ __launch_bounds__(256, 1)
void k_qkv_pers(const float* __restrict__ bias) {
    extern __shared__ char sm8[];
    const uint32_t sb = smem_u32(sm8);
    const int chunk = blockIdx.y;
    const int grp   = blockIdx.x;
    const int tid = threadIdx.x, warp = tid >> 5, lane = tid & 31;
    const int tt = lane & 7, sel = lane >> 3;
    const int mh = warp & 1, nq = warp >> 1;
    const int qr = lane >> 2, qc = 2 * (lane & 3);

    {
        const uint4* srch = g_wqh + (size_t)chunk * 1536;
        const uint4* srcl = g_wql + (size_t)chunk * 1536;
        #pragma unroll
        for (int u = 0; u < 6; u++) {
            int i = tid + u * 256;
            int row = i / 24, c = i - row * 24;
            *(uint4*)(sm8 + 51200 + row * 400 + c * 16)         = srch[i];
            *(uint4*)(sm8 + 51200 + 25600 + row * 400 + c * 16) = srcl[i];
        }
    }
    __syncthreads();
    uint32_t Bh[12][4], Bl[12][4];
    {
        const uint32_t bRow = (uint32_t)(nq * 16 + (sel >> 1) * 8 + tt) * 400
                              + (sel & 1) * 16;
        uint32_t bH = sb + 51200 + bRow;
        #pragma unroll
        for (int ks = 0; ks < 12; ks++) {
            ldsm4(Bh[ks], bH + ks * 32);
            ldsm4(Bl[ks], bH + 25600 + ks * 32);
        }
    }

    const int s  = chunk / 3, r3 = chunk - 3 * s;
    const int h  = 2 * r3 + (nq >> 1);
    const int dbase = (nq & 1) * 16;
    const float sc = (s == 0) ? 0.17677669529663687f : 1.0f;
    float2 bias0 = *(const float2*)&bias[chunk * 64 + nq * 16 + qc];
    float2 bias1 = *(const float2*)&bias[chunk * 64 + nq * 16 + 8 + qc];

    const int win0 = grp * QP_W;
    {
        const uint4* sh2 = g_xhi + (size_t)win0 * 1536;
        const uint4* sl2 = g_xlo + (size_t)win0 * 1536;
        #pragma unroll
        for (int u = 0; u < 6; u++) {
            int i = tid + u * 256;
            int t = i / 24, c = i - t * 24;
            CP_ASYNC16(sb + t * 400 + c * 16,         (const void*)(sh2 + i));
            CP_ASYNC16(sb + 25600 + t * 400 + c * 16, (const void*)(sl2 + i));
        }
        CP_COMMIT();
    }

    for (int i = 0; i < QP_W; i++) {
        const int win = win0 + i;
        CP_WAIT0();
        __syncthreads();
        if (i + 1 < QP_W) {
            uint32_t nb = sb + (uint32_t)((i + 1) & 1) * 51200;
            const uint4* sh2 = g_xhi + (size_t)(win + 1) * 1536;
            const uint4* sl2 = g_xlo + (size_t)(win + 1) * 1536;
            #pragma unroll
            for (int u = 0; u < 6; u++) {
                int ii = tid + u * 256;
                int t = ii / 24, c = ii - t * 24;
                CP_ASYNC16(nb + t * 400 + c * 16,         (const void*)(sh2 + ii));
                CP_ASYNC16(nb + 25600 + t * 400 + c * 16, (const void*)(sl2 + ii));
            }
        }
        CP_COMMIT();

        float acc[2][2][4];
        #pragma unroll
        for (int mt = 0; mt < 2; mt++) {
            acc[mt][0][0] = bias0.x; acc[mt][0][1] = bias0.y;
            acc[mt][0][2] = bias0.x; acc[mt][0][3] = bias0.y;
            acc[mt][1][0] = bias1.x; acc[mt][1][1] = bias1.y;
            acc[mt][1][2] = bias1.x; acc[mt][1][3] = bias1.y;
        }

        const uint32_t abase = sb + (uint32_t)(i & 1) * 51200;
        #pragma unroll
        for (int ks = 0; ks < 12; ks++) {
            #pragma unroll
            for (int mt = 0; mt < 2; mt++) {
                uint32_t ar = abase
                    + (uint32_t)(mh * 32 + mt * 16 + (sel & 1) * 8 + tt) * 400
                    + (sel >> 1) * 16 + ks * 32;
                uint32_t ah[4], al[4];
                ldsm4(ah, ar);
                ldsm4(al, ar + 25600);
                mma16816(acc[mt][0], ah, Bh[ks][0], Bh[ks][1]);
                mma16816(acc[mt][0], al, Bh[ks][0], Bh[ks][1]);
                mma16816(acc[mt][0], ah, Bl[ks][0], Bl[ks][1]);
                mma16816(acc[mt][1], ah, Bh[ks][2], Bh[ks][3]);
                mma16816(acc[mt][1], al, Bh[ks][2], Bh[ks][3]);
                mma16816(acc[mt][1], ah, Bl[ks][2], Bl[ks][3]);
            }
        }

        // epilogue: bf16 hi/lo plane store [plane(win,s,h)][row t][d pair]
        uint32_t* ph = g_sh32 + (((size_t)win * 3 + s) * 6 + h) * 1024;
        uint32_t* pl = g_sl32 + (((size_t)win * 3 + s) * 6 + h) * 1024;
        #pragma unroll
        for (int mt = 0; mt < 2; mt++) {
            int t0 = mh * 32 + mt * 16 + qr;
            #pragma unroll
            for (int nt = 0; nt < 2; nt++) {
                int d = dbase + nt * 8 + qc;
                uint32_t hi, lo;
                split2(acc[mt][nt][0] * sc, acc[mt][nt][1] * sc, hi, lo);
                ph[t0 * 16 + (d >> 1)] = hi;
                pl[t0 * 16 + (d >> 1)] = lo;
                split2(acc[mt][nt][2] * sc, acc[mt][nt][3] * sc, hi, lo);
                ph[(t0 + 8) * 16 + (d >> 1)] = hi;
                pl[(t0 + 8) * 16 + (d >> 1)] = lo;
            }
        }
    }
}

// =====================================================================
// Kernel 2: tensor-core attention. grid=(4608,6), block=128 (4 warps).
// Warp w owns S rows 16w..16w+15. Q/K/V hi/lo staged in pitch-80 smem.
// Softmax in C-fragments; P repacked in-register to A-frags for PV.
// smem planes: qh ql kh kl vh vl @ 5120 B each, tb[225]f, ids[64]i.
// =====================================================================
constexpr int AT_SMEM = 6 * 5120 + 228 * 4 + 64 * 4;   // 31888

__global__ __launch_bounds__(128, 4)
void k_attn_mma(const float* __restrict__ tbl) {
    extern __shared__ char smc[];
    const uint32_t sb = smem_u32(smc);
    float* tb = (float*)(smc + 30720);
    int*  ids = (int*)(smc + 30720 + 912);

    const int b_ = blockIdx.x;
    const int h  = blockIdx.y;
    const int tid  = threadIdx.x;
    const int warp = tid >> 5;
    const int lane = tid & 31;
    const int tt = lane & 7, sel = lane >> 3;
    const int qr = lane >> 2, ql2 = lane & 3;

    // ---- stage 6 planes (q/k/v x hi/lo), 256 chunks each ----
    #pragma unroll
    for (int s = 0; s < 3; s++) {
        const uint4* srch = (const uint4*)(g_sh32 + (((size_t)b_ * 3 + s) * 6 + h) * 1024);
        const uint4* srcl = (const uint4*)(g_sl32 + (((size_t)b_ * 3 + s) * 6 + h) * 1024);
        uint32_t dsth = sb + s * 10240;
        #pragma unroll
        for (int u = 0; u < 2; u++) {
            int j = tid + u * 128;
            int row = j >> 2, c = j & 3;
            CP_ASYNC16(dsth + row * 80 + c * 16,        (const void*)(srch + j));
            CP_ASYNC16(dsth + 5120 + row * 80 + c * 16, (const void*)(srcl + j));
        }
    }
    CP_COMMIT();
    for (int i = tid; i < 225; i += 128) tb[i] = tbl[i * 6 + h];
    if (tid < 64) {
        int wh = (b_ % 576) / 24, ww = b_ % 24;
        int gh = wh * 8 + (tid >> 3), gw = ww * 8 + (tid & 7);
        int rh = gh < (H_ - 8) ? 0 : (gh < (H_ - 4) ? 1 : 2);
        int rw = gw < (W_ - 8) ? 0 : (gw < (W_ - 4) ? 1 : 2);
        ids[tid] = rh * 3 + rw;
    }
    CP_WAIT0();
    __syncthreads();

    // ---- Q A-fragments (2 k-steps, hi/lo) ----
    uint32_t Ah[2][4], Al[2][4];
    #pragma unroll
    for (int ks = 0; ks < 2; ks++) {
        uint32_t ar = sb + (uint32_t)(warp * 16 + (sel & 1) * 8 + tt) * 80
                      + ks * 32 + (sel >> 1) * 16;
        ldsm4(Ah[ks], ar);
        ldsm4(Al[ks], ar + 5120);
    }

    // ---- S = QK^T (8 n-tiles of 8 keys) ----
    float s[8][4];
    #pragma unroll
    for (int nt = 0; nt < 8; nt++) {
        s[nt][0] = s[nt][1] = s[nt][2] = s[nt][3] = 0.f;
        uint32_t ka = sb + 10240 + (uint32_t)(nt * 8 + tt) * 80 + sel * 16;
        uint32_t Bh4[4], Bl4[4];
        ldsm4(Bh4, ka);
        ldsm4(Bl4, ka + 5120);
        mma16816(s[nt], Ah[0], Bh4[0], Bh4[1]);
        mma16816(s[nt], Al[0], Bh4[0], Bh4[1]);
        mma16816(s[nt], Ah[0], Bl4[0], Bl4[1]);
        mma16816(s[nt], Ah[1], Bh4[2], Bh4[3]);
        mma16816(s[nt], Al[1], Bh4[2], Bh4[3]);
        mma16816(s[nt], Ah[1], Bl4[2], Bl4[3]);
    }

    // ---- softmax in fragments ----
    const int r0 = 16 * warp + qr, r1 = r0 + 8;
    const int base0 = ((r0 >> 3) + 7) * 15 + (r0 & 7) + 7;
    const int base1 = ((r1 >> 3) + 7) * 15 + (r1 & 7) + 7;
    const int idn0 = ids[r0], idn1 = ids[r1];
    float sum0 = 0.f, sum1 = 0.f;
    #pragma unroll
    for (int nt = 0; nt < 8; nt++) {
        int m0 = nt * 8 + 2 * ql2;
        int idm0 = ids[m0], idm1 = ids[m0 + 1];
        int mo0 = nt * 15 + 2 * ql2, mo1 = mo0 + 1;
        float e0 = __expf(s[nt][0] + tb[base0 - mo0] - (idn0 != idm0 ? 100.f : 0.f));
        float e1 = __expf(s[nt][1] + tb[base0 - mo1] - (idn0 != idm1 ? 100.f : 0.f));
        float e2 = __expf(s[nt][2] + tb[base1 - mo0] - (idn1 != idm0 ? 100.f : 0.f));
        float e3 = __expf(s[nt][3] + tb[base1 - mo1] - (idn1 != idm1 ? 100.f : 0.f));
        s[nt][0] = e0; s[nt][1] = e1; s[nt][2] = e2; s[nt][3] = e3;
        sum0 += e0 + e1;
        sum1 += e2 + e3;
    }
    sum0 += __shfl_xor_sync(0xffffffff, sum0, 1);
    sum0 += __shfl_xor_sync(0xffffffff, sum0, 2);
    sum1 += __shfl_xor_sync(0xffffffff, sum1, 1);
    sum1 += __shfl_xor_sync(0xffffffff, sum1, 2);
    const float inv0 = 1.0f / sum0, inv1 = 1.0f / sum1;

    // ---- O = P V (4 d-tiles) ----
    float o[4][4];
    #pragma unroll
    for (int nt = 0; nt < 4; nt++)
        o[nt][0] = o[nt][1] = o[nt][2] = o[nt][3] = 0.f;

    #pragma unroll
    for (int kt = 0; kt < 4; kt++) {
        // pack P fragments (C->A identity) with hi/lo split
        uint32_t Ph[4], Pl[4];
        split2(s[2 * kt][0],     s[2 * kt][1],     Ph[0], Pl[0]);
        split2(s[2 * kt][2],     s[2 * kt][3],     Ph[1], Pl[1]);
        split2(s[2 * kt + 1][0], s[2 * kt + 1][1], Ph[2], Pl[2]);
        split2(s[2 * kt + 1][2], s[2 * kt + 1][3], Ph[3], Pl[3]);
        #pragma unroll
        for (int p = 0; p < 2; p++) {
            uint32_t va = sb + 20480
                + (uint32_t)(kt * 16 + (sel & 1) * 8 + tt) * 80
                + (uint32_t)(2 * p + (sel >> 1)) * 16;
            uint32_t Vh4[4], Vl4[4];
            ldsm4t(Vh4, va);
            ldsm4t(Vl4, va + 5120);
            mma16816(o[2 * p],     Ph, Vh4[0], Vh4[1]);
            mma16816(o[2 * p],     Pl, Vh4[0], Vh4[1]);
            mma16816(o[2 * p],     Ph, Vl4[0], Vl4[1]);
            mma16816(o[2 * p + 1], Ph, Vh4[2], Vh4[3]);
            mma16816(o[2 * p + 1], Pl, Vh4[2], Vh4[3]);
            mma16816(o[2 * p + 1], Ph, Vl4[2], Vl4[3]);
        }
    }

    // ---- epilogue: normalized O -> g_ahi/g_alo (proj input layout) ----
    uint32_t* dh = (uint32_t*)(g_ahi + (size_t)b_ * 1536);
    uint32_t* dl = (uint32_t*)(g_alo + (size_t)b_ * 1536);
    #pragma unroll
    for (int nt = 0; nt < 4; nt++) {
        int col = h * 32 + nt * 8 + 2 * ql2;
        uint32_t hi, lo;
        split2(o[nt][0] * inv0, o[nt][1] * inv0, hi, lo);
        dh[r0 * 96 + (col >> 1)] = hi;
        dl[r0 * 96 + (col >> 1)] = lo;
        split2(o[nt][2] * inv1, o[nt][3] * inv1, hi, lo);
        dh[r1 * 96 + (col >> 1)] = hi;
        dl[r1 * 96 + (col >> 1)] = lo;
    }
}

// =====================================================================
// Kernel 3: chunk-persistent proj GEMM + reverse-roll scatter (R14)
// =====================================================================
constexpr int PP_W  = 48;
constexpr int PP_NG = 96;

__global__ __launch_bounds__(256, 1)
void k_proj_pers(const float* __restrict__ bias, float* __restrict__ out) {
    extern __shared__ char sm8[];
    const uint32_t sb = smem_u32(sm8);
    float* res = (float*)(sm8 + 102400);   // [64 o][66 t]
    __shared__ int soff[64];
    const int chunk = blockIdx.y;
    const int grp   = blockIdx.x;
    const int tid = threadIdx.x, warp = tid >> 5, lane = tid & 31;
    const int tt = lane & 7, sel = lane >> 3;
    const int mh = warp & 1, nq = warp >> 1;
    const int qr = lane >> 2, qc = 2 * (lane & 3);

    {
        const uint4* srch = g_wph + (size_t)chunk * 1536;
        const uint4* srcl = g_wpl + (size_t)chunk * 1536;
        #pragma unroll
        for (int u = 0; u < 6; u++) {
            int i = tid + u * 256;
            int row = i / 24, c = i - row * 24;
            *(uint4*)(sm8 + 51200 + row * 400 + c * 16)         = srch[i];
            *(uint4*)(sm8 + 51200 + 25600 + row * 400 + c * 16) = srcl[i];
        }
    }
    __syncthreads();
    uint32_t Bh[12][4], Bl[12][4];
    {
        const uint32_t bRow = (uint32_t)(nq * 16 + (sel >> 1) * 8 + tt) * 400
                              + (sel & 1) * 16;
        uint32_t bH = sb + 51200 + bRow;
        #pragma unroll
        for (int ks = 0; ks < 12; ks++) {
            ldsm4(Bh[ks], bH + ks * 32);
            ldsm4(Bl[ks], bH + 25600 + ks * 32);
        }
    }

    float2 bias0 = *(const float2*)&bias[chunk * 64 + nq * 16 + qc];
    float2 bias1 = *(const float2*)&bias[chunk * 64 + nq * 16 + 8 + qc];

    const int win0 = grp * PP_W;
    {
        const uint4* sh2 = g_ahi + (size_t)win0 * 1536;
        const uint4* sl2 = g_alo + (size_t)win0 * 1536;
        #pragma unroll
        for (int u = 0; u < 6; u++) {
            int i = tid + u * 256;
            int t = i / 24, c = i - t * 24;
            CP_ASYNC16(sb + t * 400 + c * 16,         (const void*)(sh2 + i));
            CP_ASYNC16(sb + 25600 + t * 400 + c * 16, (const void*)(sl2 + i));
        }
        CP_COMMIT();
    }

    for (int i = 0; i < PP_W; i++) {
        const int win = win0 + i;
        CP_WAIT0();
        __syncthreads();
        if (tid < 64) {
            int wh = (win % 576) / 24, ww = win % 24;
            int sh = wh * 8 + (tid >> 3) + SS_; if (sh >= H_) sh -= H_;
            int sw = ww * 8 + (tid & 7)  + SS_; if (sw >= W_) sw -= W_;
            soff[tid] = sh * W_ + sw;
        }
        if (i + 1 < PP_W) {
            uint32_t nb = sb + (uint32_t)((i + 1) & 1) * 51200;
            const uint4* sh2 = g_ahi + (size_t)(win + 1) * 1536;
            const uint4* sl2 = g_alo + (size_t)(win + 1) * 1536;
            #pragma unroll
            for (int u = 0; u < 6; u++) {
                int ii = tid + u * 256;
                int t = ii / 24, c = ii - t * 24;
                CP_ASYNC16(nb + t * 400 + c * 16,         (const void*)(sh2 + ii));
                CP_ASYNC16(nb + 25600 + t * 400 + c * 16, (const void*)(sl2 + ii));
            }
        }
        CP_COMMIT();

        float acc[2][2][4];
        #pragma unroll
        for (int mt = 0; mt < 2; mt++) {
            acc[mt][0][0] = bias0.x; acc[mt][0][1] = bias0.y;
            acc[mt][0][2] = bias0.x; acc[mt][0][3] = bias0.y;
            acc[mt][1][0] = bias1.x; acc[mt][1][1] = bias1.y;
            acc[mt][1][2] = bias1.x; acc[mt][1][3] = bias1.y;
        }

        const uint32_t abase = sb + (uint32_t)(i & 1) * 51200;
        #pragma unroll
        for (int ks = 0; ks < 12; ks++) {
            #pragma unroll
            for (int mt = 0; mt < 2; mt++) {
                uint32_t ar = abase
                    + (uint32_t)(mh * 32 + mt * 16 + (sel & 1) * 8 + tt) * 400
                    + (sel >> 1) * 16 + ks * 32;
                uint32_t ah[4], al[4];
                ldsm4(ah, ar);
                ldsm4(al, ar + 25600);
                mma16816(acc[mt][0], ah, Bh[ks][0], Bh[ks][1]);
                mma16816(acc[mt][0], al, Bh[ks][0], Bh[ks][1]);
                mma16816(acc[mt][0], ah, Bl[ks][0], Bl[ks][1]);
                mma16816(acc[mt][1], ah, Bh[ks][2], Bh[ks][3]);
                mma16816(acc[mt][1], al, Bh[ks][2], Bh[ks][3]);
                mma16816(acc[mt][1], ah, Bl[ks][2], Bl[ks][3]);
            }
        }

        #pragma unroll
        for (int mt = 0; mt < 2; mt++) {
            int t0 = mh * 32 + mt * 16 + qr;
            #pragma unroll
            for (int nt = 0; nt < 2; nt++) {
                int o = nq * 16 + nt * 8 + qc;
                res[o * 66 + t0]           = acc[mt][nt][0];
                res[(o + 1) * 66 + t0]     = acc[mt][nt][1];
                res[o * 66 + t0 + 8]       = acc[mt][nt][2];
                res[(o + 1) * 66 + t0 + 8] = acc[mt][nt][3];
            }
        }
        __syncthreads();

        float* outb = out + (size_t)(win / 576) * C_ * HW_;
        #pragma unroll
        for (int it = 0; it < 16; it++) {
            int idx = tid + it * 256;
            int o = idx >> 6, t = idx & 63;
            outb[(chunk * 64 + o) * HW_ + soff[t]] = res[o * 66 + t];
        }
    }
}

// =====================================================================
extern "C" void kernel_launch(void* const* d_in, const int* in_sizes, int n_in,
                              void* d_out, int out_size) {
    const float* x      = (const float*)d_in[0];
    const float* qkv_w  = (const float*)d_in[1];
    const float* qkv_b  = (const float*)d_in[2];
    const float* proj_w = (const float*)d_in[3];
    const float* proj_b = (const float*)d_in[4];
    const float* tbl    = (const float*)d_in[5];
    float* out = (float*)d_out;

    cudaFuncSetAttribute(k_qkv_pers,  cudaFuncAttributeMaxDynamicSharedMemorySize, 102400);
    cudaFuncSetAttribute(k_attn_mma,  cudaFuncAttributeMaxDynamicSharedMemorySize, AT_SMEM);
    cudaFuncSetAttribute(k_proj_pers, cudaFuncAttributeMaxDynamicSharedMemorySize, 119296);

    k_split_w<<<72, 256>>>(qkv_w, proj_w);
    k_split_x<<<NWIN, 256>>>(x);
    k_qkv_pers<<<dim3(QP_NG, 9), 256, 102400>>>(qkv_b);
    k_attn_mma<<<dim3(NWIN, 6), 128, AT_SMEM>>>(tbl);
    k_proj_pers<<<dim3(PP_NG, 3), 256, 119296>>>(proj_b, out);
}